// round 16
// baseline (speedup 1.0000x reference)
#include <cuda_runtime.h>
#include <cuda_fp16.h>
#include <cstdint>

#define B_ 4
#define N_ 1024
#define C_ 768
#define H_ 12
#define BN 4096
#define SCALE 0.125f

// ---------------- scratch (static device globals; no allocations) ----------
__device__ __align__(16) __half g_Qh[(size_t)B_*H_*N_*128];  // SCALE folded
__device__ __align__(16) __half g_Kh[(size_t)B_*H_*N_*128];
__device__ __align__(16) __half g_Vh[(size_t)B_*H_*N_*128];

__device__ __align__(16) __half g_Xh[(size_t)2*BN*C_];
__device__ __align__(16) __half g_Wqh[(size_t)3*C_*C_];
__device__ __align__(16) __half g_Wql[(size_t)3*C_*C_];
__device__ __align__(16) __half g_Wph[(size_t)C_*C_];
__device__ __align__(16) __half g_Oh[(size_t)2*BN*C_];

// ---------------- helpers ---------------------------------------------------
__device__ __forceinline__ uint32_t smem_u32(const void* p) {
    uint32_t a;
    asm("{ .reg .u64 t; cvta.to.shared.u64 t, %1; cvt.u32.u64 %0, t; }"
        : "=r"(a) : "l"(p));
    return a;
}
__device__ __forceinline__ uint32_t swz(uint32_t o) {   // 128B-row swizzle
    return o ^ ((o >> 3) & 0x70);
}
__device__ __forceinline__ void cpa16(uint32_t dst, const void* src) {
    asm volatile("cp.async.cg.shared.global [%0], [%1], 16;" :: "r"(dst), "l"(src));
}
__device__ __forceinline__ void cpa_commit() {
    asm volatile("cp.async.commit_group;" ::: "memory");
}
template<int N>
__device__ __forceinline__ void cpa_wait() {
    asm volatile("cp.async.wait_group %0;" :: "n"(N) : "memory");
}
__device__ __forceinline__ void ldsm_x4(uint32_t* r, uint32_t addr) {
    asm volatile("ldmatrix.sync.aligned.m8n8.x4.shared.b16 {%0,%1,%2,%3}, [%4];"
                 : "=r"(r[0]), "=r"(r[1]), "=r"(r[2]), "=r"(r[3]) : "r"(addr));
}
__device__ __forceinline__ void ldsm_x4_t(uint32_t* r, uint32_t addr) {
    asm volatile("ldmatrix.sync.aligned.m8n8.x4.trans.shared.b16 {%0,%1,%2,%3}, [%4];"
                 : "=r"(r[0]), "=r"(r[1]), "=r"(r[2]), "=r"(r[3]) : "r"(addr));
}
__device__ __forceinline__ void mma16816(float* d, const uint32_t* a, const uint32_t* b) {
    asm volatile(
        "mma.sync.aligned.m16n8k16.row.col.f32.f16.f16.f32 "
        "{%0,%1,%2,%3}, {%4,%5,%6,%7}, {%8,%9}, {%0,%1,%2,%3};"
        : "+f"(d[0]), "+f"(d[1]), "+f"(d[2]), "+f"(d[3])
        : "r"(a[0]), "r"(a[1]), "r"(a[2]), "r"(a[3]), "r"(b[0]), "r"(b[1]));
}
__device__ __forceinline__ uint32_t pack_h2(float a, float b) {
    __half2 t = __floats2half2_rn(a, b);
    return *(uint32_t*)&t;
}

// ---------------------------------------------------------------------------
// fused split kernel: x1,x2,Wproj -> fp16 hi only; Wqkv -> fp16 hi/lo
// ---------------------------------------------------------------------------
#define NX4  (BN * C_ / 4)          // 786432 -> 3072 blocks

__global__ __launch_bounds__(256) void split_all(
    const float* __restrict__ x1, const float* __restrict__ x2,
    const float* __restrict__ Wq, const float* __restrict__ Wp)
{
    int bid = blockIdx.x;
    const float* src;
    __half *hi, *lo;
    size_t off4;
    int i;
    bool wantLo = false;
    if (bid < 3072) {
        src = x1; hi = g_Xh; lo = nullptr; off4 = 0;
        i = bid * 256 + threadIdx.x;
    } else if (bid < 6144) {
        src = x2; hi = g_Xh; lo = nullptr; off4 = NX4;
        i = (bid - 3072) * 256 + threadIdx.x;
    } else if (bid < 7872) {
        src = Wq; hi = g_Wqh; lo = g_Wql; off4 = 0; wantLo = true;
        i = (bid - 6144) * 256 + threadIdx.x;
    } else {
        src = Wp; hi = g_Wph; lo = nullptr; off4 = 0;
        i = (bid - 7872) * 256 + threadIdx.x;
    }
    float4 v = ((const float4*)src)[i];
    size_t o = off4 + (size_t)i;
    ((uint32_t*)hi)[o*2 + 0] = pack_h2(v.x, v.y);
    ((uint32_t*)hi)[o*2 + 1] = pack_h2(v.z, v.w);
    if (wantLo) {
        __half h0 = __float2half(v.x);
        __half h1 = __float2half(v.y);
        __half h2 = __float2half(v.z);
        __half h3 = __float2half(v.w);
        ((uint32_t*)lo)[o*2 + 0] = pack_h2(v.x - __half2float(h0), v.y - __half2float(h1));
        ((uint32_t*)lo)[o*2 + 1] = pack_h2(v.z - __half2float(h2), v.w - __half2float(h3));
    }
}

// ---------------------------------------------------------------------------
// qkv GEMM: 128x128 CTA tile, 128 threads (4 warps, 64x64), K-chunk 64
// (128B-row stages), 2-stage cp.async, 12 iterations.
// Q,K tiles: 2-term (Xh*Wh + Xh*Wl).  V tiles: 1-term.
// ---------------------------------------------------------------------------
__device__ __forceinline__ void gemm_issue_chunk(
    uint32_t sbase, const __half* Ah, const __half* Bh, const __half* Bl,
    int m0, int c0, int kc, int tid, bool loadBl)
{
#pragma unroll
    for (int it = 0; it < 8; it++) {
        int idx = tid + it * 128;          // 0..1023: 128 rows x 8 16B-chunks
        int r = idx >> 3, ch8 = idx & 7;
        uint32_t so = swz((uint32_t)(r * 128 + ch8 * 16));
        const size_t aoff = (size_t)(m0 + r) * C_ + kc + ch8 * 8;
        const size_t boff = (size_t)(c0 + r) * C_ + kc + ch8 * 8;
        cpa16(sbase +     0 + so, Ah + aoff);
        cpa16(sbase + 16384 + so, Bh + boff);
        if (loadBl) cpa16(sbase + 32768 + so, Bl + boff);
    }
    cpa_commit();
}

__global__ __launch_bounds__(128, 2) void qkv_gemm(const float* __restrict__ bias)
{
    extern __shared__ char sm[];
    const uint32_t sb = smem_u32(sm) + 1024;
    const int tid = threadIdx.x;
    const int lane = tid & 31, wid = tid >> 5;
    const int wm = wid & 1, wn = wid >> 1;
    const int stream = blockIdx.z;
    const int m0 = blockIdx.y * 128;
    const int c0 = blockIdx.x * 128;
    const int s_tile = c0 / C_;                 // uniform per CTA
    const bool useBl = (s_tile < 2);            // Q,K 2-term; V 1-term

    const __half* __restrict__ Ah = g_Xh + (size_t)stream * BN * C_;
    const __half* __restrict__ Bh = g_Wqh;
    const __half* __restrict__ Bl = g_Wql;

    float acc[4][8][4];
#pragma unroll
    for (int i = 0; i < 4; i++)
#pragma unroll
        for (int j = 0; j < 8; j++)
#pragma unroll
            for (int k = 0; k < 4; k++) acc[i][j][k] = 0.f;

    const int a_r  = wm*64 + (lane & 15);
    const int a_cb = (lane >> 4) * 16;
    const int b_r  = wn*64 + (lane & 7) + ((lane >> 4) & 1)*8;
    const int b_cb = ((lane >> 3) & 1) * 16;

    const int NCH = C_ / 64;   // 12
    gemm_issue_chunk(sb, Ah, Bh, Bl, m0, c0, 0, tid, useBl);

    for (int ch = 0; ch < NCH; ch++) {
        const uint32_t stb = (uint32_t)(ch & 1) * 49152u;
        cpa_wait<0>();
        __syncthreads();
        if (ch + 1 < NCH)
            gemm_issue_chunk(sb + ((ch + 1) & 1) * 49152u,
                             Ah, Bh, Bl, m0, c0, (ch + 1) * 64, tid, useBl);

#pragma unroll
        for (int kk = 0; kk < 4; kk++) {
            uint32_t bfh[16], bfl[16];
#pragma unroll
            for (int p = 0; p < 4; p++) {
                uint32_t bo = swz((uint32_t)((b_r + p*16) * 128 + kk*32 + b_cb));
                ldsm_x4(&bfh[p*4], sb + stb + 16384 + bo);
                if (useBl) ldsm_x4(&bfl[p*4], sb + stb + 32768 + bo);
            }
#pragma unroll
            for (int mf = 0; mf < 4; mf++) {
                uint32_t ao = swz((uint32_t)((a_r + mf*16) * 128 + kk*32 + a_cb));
                uint32_t ah[4];
                ldsm_x4(ah, sb + stb + ao);
#pragma unroll
                for (int p = 0; p < 4; p++) {
                    mma16816(acc[mf][2*p],   ah, &bfh[4*p]);
                    mma16816(acc[mf][2*p+1], ah, &bfh[4*p+2]);
                }
                if (useBl) {
#pragma unroll
                    for (int p = 0; p < 4; p++) {
                        mma16816(acc[mf][2*p],   ah, &bfl[4*p]);
                        mma16816(acc[mf][2*p+1], ah, &bfl[4*p+2]);
                    }
                }
            }
        }
    }
    __syncthreads();

    float* Osm = (float*)(sm + 1024);      // [128][132]
#pragma unroll
    for (int mf = 0; mf < 4; mf++) {
#pragma unroll
        for (int nf = 0; nf < 8; nf++) {
            int row = wm*64 + mf*16 + (lane >> 2);
            int col = wn*64 + nf*8 + (lane & 3)*2;
            Osm[row       * 132 + col    ] = acc[mf][nf][0];
            Osm[row       * 132 + col + 1] = acc[mf][nf][1];
            Osm[(row + 8) * 132 + col    ] = acc[mf][nf][2];
            Osm[(row + 8) * 132 + col + 1] = acc[mf][nf][3];
        }
    }
    __syncthreads();

#pragma unroll
    for (int it = 0; it < 32; it++) {
        int idx = tid + it * 128;
        int r = idx >> 5, j4 = idx & 31;
        float4 v = *(float4*)&Osm[r * 132 + j4 * 4];
        float4 bb = *(const float4*)&bias[c0 + j4 * 4];
        v.x += bb.x; v.y += bb.y; v.z += bb.z; v.w += bb.w;
        int m = m0 + r;
        int cg = c0 + j4 * 4;
        int rem = cg - s_tile * C_;
        int h = rem >> 6, d = rem & 63;
        if (s_tile == 0) { v.x *= SCALE; v.y *= SCALE; v.z *= SCALE; v.w *= SCALE; }
        uint2 hv;
        hv.x = pack_h2(v.x, v.y); hv.y = pack_h2(v.z, v.w);
        int b = m >> 10, n = m & 1023;
        size_t base = ((size_t)(b * H_ + h) * N_ + n) * 128 + stream * 64 + d;
        __half* buf = (s_tile == 0) ? g_Qh : (s_tile == 1) ? g_Kh : g_Vh;
        *(uint2*)&buf[base] = hv;
    }
}

// ---------------------------------------------------------------------------
// proj GEMM: 128x128 CTA tile (retiled for single-wave), 128 threads
// (4 warps, 64x64 each), K-chunk 64, 2-stage cp.async, 1-term (Oh*Wh).
// grid (6, 32, 2) = 384 CTAs @ 3/SM = 0.86 waves.
// stage = A 16KB + Bh 16KB = 32KB; alloc = 1024 + max(2x32768, Osm 67584).
// ---------------------------------------------------------------------------
__device__ __forceinline__ void proj_issue_chunk(
    uint32_t sbase, const __half* Ah, const __half* Bh,
    int m0, int c0, int kc, int tid)
{
#pragma unroll
    for (int it = 0; it < 8; it++) {
        int idx = tid + it * 128;          // 0..1023: 128 rows x 8 16B-chunks
        int r = idx >> 3, ch8 = idx & 7;
        uint32_t so = swz((uint32_t)(r * 128 + ch8 * 16));
        cpa16(sbase +     0 + so, Ah + (size_t)(m0 + r) * C_ + kc + ch8 * 8);
        cpa16(sbase + 16384 + so, Bh + (size_t)(c0 + r) * C_ + kc + ch8 * 8);
    }
    cpa_commit();
}

__global__ __launch_bounds__(128, 3) void proj_gemm(const float* __restrict__ bias,
                                                    float* __restrict__ outp)
{
    extern __shared__ char sm[];
    const uint32_t sb = smem_u32(sm) + 1024;
    const int tid = threadIdx.x;
    const int lane = tid & 31, wid = tid >> 5;
    const int wm = wid & 1, wn = wid >> 1;
    const int stream = blockIdx.z;
    const int m0 = blockIdx.y * 128;
    const int c0 = blockIdx.x * 128;

    const __half* __restrict__ Ah = g_Oh + (size_t)stream * BN * C_;
    const __half* __restrict__ Bh = g_Wph;

    float acc[4][8][4];
#pragma unroll
    for (int i = 0; i < 4; i++)
#pragma unroll
        for (int j = 0; j < 8; j++)
#pragma unroll
            for (int k = 0; k < 4; k++) acc[i][j][k] = 0.f;

    const int a_r  = wm*64 + (lane & 15);
    const int a_cb = (lane >> 4) * 16;
    const int b_r  = wn*64 + (lane & 7) + ((lane >> 4) & 1)*8;
    const int b_cb = ((lane >> 3) & 1) * 16;

    const int NCH = C_ / 64;   // 12
    proj_issue_chunk(sb, Ah, Bh, m0, c0, 0, tid);

    for (int ch = 0; ch < NCH; ch++) {
        const uint32_t stb = (uint32_t)(ch & 1) * 32768u;
        cpa_wait<0>();
        __syncthreads();
        if (ch + 1 < NCH)
            proj_issue_chunk(sb + ((ch + 1) & 1) * 32768u,
                             Ah, Bh, m0, c0, (ch + 1) * 64, tid);

#pragma unroll
        for (int kk = 0; kk < 4; kk++) {
            uint32_t bfh[16];
#pragma unroll
            for (int p = 0; p < 4; p++) {
                uint32_t bo = swz((uint32_t)((b_r + p*16) * 128 + kk*32 + b_cb));
                ldsm_x4(&bfh[p*4], sb + stb + 16384 + bo);
            }
#pragma unroll
            for (int mf = 0; mf < 4; mf++) {
                uint32_t ao = swz((uint32_t)((a_r + mf*16) * 128 + kk*32 + a_cb));
                uint32_t ah[4];
                ldsm_x4(ah, sb + stb + ao);
#pragma unroll
                for (int p = 0; p < 4; p++) {
                    mma16816(acc[mf][2*p],   ah, &bfh[4*p]);
                    mma16816(acc[mf][2*p+1], ah, &bfh[4*p+2]);
                }
            }
        }
    }
    __syncthreads();

    float* Osm = (float*)(sm + 1024);      // [128][132]
#pragma unroll
    for (int mf = 0; mf < 4; mf++) {
#pragma unroll
        for (int nf = 0; nf < 8; nf++) {
            int row = wm*64 + mf*16 + (lane >> 2);
            int col = wn*64 + nf*8 + (lane & 3)*2;
            Osm[row       * 132 + col    ] = acc[mf][nf][0];
            Osm[row       * 132 + col + 1] = acc[mf][nf][1];
            Osm[(row + 8) * 132 + col    ] = acc[mf][nf][2];
            Osm[(row + 8) * 132 + col + 1] = acc[mf][nf][3];
        }
    }
    __syncthreads();

    float* Y = outp + (size_t)stream * BN * C_;
#pragma unroll
    for (int it = 0; it < 32; it++) {
        int idx = tid + it * 128;
        int r = idx >> 5, j4 = idx & 31;
        float4 v = *(float4*)&Osm[r * 132 + j4 * 4];
        float4 bb = *(const float4*)&bias[c0 + j4 * 4];
        v.x += bb.x; v.y += bb.y; v.z += bb.z; v.w += bb.w;
        *(float4*)&Y[(size_t)(m0 + r) * C_ + c0 + j4 * 4] = v;
    }
}

// ---------------------------------------------------------------------------
// flash attention (r13 proven): HMMA fp16, 128 q-rows/CTA, 8 warps x 16 rows.
// S = Qh*Kh (1-term).  PV 1-term.  Warp-local softmax, register P,
// cp.async 2-stage K/V, 1 barrier/tile.  smem 98304 B.
// ---------------------------------------------------------------------------
#define ASTG_ 32768u
#define AKH_ 0u
#define AVH_ 16384u
#define AQH_ 65536u

__device__ __forceinline__ void attn_issue_kv(
    uint32_t sb, uint32_t stb,
    const __half* kh_g, const __half* vh_g, int tid)
{
#pragma unroll
    for (int it = 0; it < 4; it++) {
        int idx = tid + it * 256;          // 0..1023: 64 rows x 16 16B-chunks
        int row = idx >> 4, ch = idx & 15;
        int src = row * 128 + ch * 8;
        uint32_t dst = stb + (uint32_t)(ch >> 3) * 8192 + swz((uint32_t)(row * 128 + (ch & 7) * 16));
        cpa16(sb + AKH_ + dst, kh_g + src);
        cpa16(sb + AVH_ + dst, vh_g + src);
    }
    cpa_commit();
}

__global__ __launch_bounds__(256, 1) void attn_mma()
{
    extern __shared__ char sm[];
    const uint32_t sb = smem_u32(sm);

    const int tid = threadIdx.x;
    const int lane = tid & 31, wr = tid >> 5;
    const int qt = blockIdx.x, bh = blockIdx.y;
    const int b = bh / H_, h = bh - b * H_;
    const size_t kvb = (size_t)bh * N_ * 128;

    const __half* kh_g = g_Kh + kvb;
    const __half* vh_g = g_Vh + kvb;

    attn_issue_kv(sb, 0, kh_g, vh_g, tid);

    {
        const __half* qh_g = g_Qh + kvb + (size_t)qt * 128 * 128;
#pragma unroll
        for (int it = 0; it < 8; it++) {
            int idx = tid + it * 256;
            int row = idx >> 4, ch = idx & 15;
            uint32_t dst = (uint32_t)(ch >> 3) * 16384 + swz((uint32_t)(row * 128 + (ch & 7) * 16));
            *(uint4*)(sm + AQH_ + dst) = *(const uint4*)(qh_g + row * 128 + ch * 8);
        }
    }

    float m0r = -1e30f, m1r = -1e30f, l0r = 0.f, l1r = 0.f;
    float o[16][4];
#pragma unroll
    for (int i = 0; i < 16; i++)
#pragma unroll
        for (int j = 0; j < 4; j++) o[i][j] = 0.f;

    const int qrow = wr * 16 + (lane & 15);
    const int k_r  = (lane & 7) + ((lane >> 4) & 1) * 8;
    const int k_cb = ((lane >> 3) & 1) * 16;

    for (int kt = 0; kt < 16; kt++) {
        const uint32_t stb = (uint32_t)(kt & 1) * ASTG_;
        cpa_wait<0>();
        __syncthreads();
        if (kt < 15)
            attn_issue_kv(sb, (uint32_t)((kt + 1) & 1) * ASTG_,
                          kh_g + (size_t)(kt + 1) * 64 * 128,
                          vh_g + (size_t)(kt + 1) * 64 * 128, tid);

        // ---- S = Q K^T : 16 rows x 64 cols per warp, k=128, 1-term ----
        float sacc[8][4];
#pragma unroll
        for (int i = 0; i < 8; i++)
#pragma unroll
            for (int j = 0; j < 4; j++) sacc[i][j] = 0.f;

#pragma unroll
        for (int k16 = 0; k16 < 8; k16++) {
            uint32_t qo = (uint32_t)(k16 >> 2) * 16384 +
                          swz((uint32_t)(qrow * 128 + (k16 & 3) * 32 + (lane >> 4) * 16));
            uint32_t ah[4];
            ldsm_x4(ah, sb + AQH_ + qo);
            uint32_t kpl = stb + (uint32_t)(k16 >> 2) * 8192;
            uint32_t kcb = (uint32_t)((k16 & 3) * 32) + k_cb;
            uint32_t kfh[16];
#pragma unroll
            for (int p = 0; p < 4; p++) {
                uint32_t ko = kpl + swz((uint32_t)((k_r + p*16) * 128) + kcb);
                ldsm_x4(&kfh[4*p], sb + AKH_ + ko);
            }
#pragma unroll
            for (int p = 0; p < 4; p++) {
                mma16816(sacc[2*p],   ah, &kfh[4*p]);
                mma16816(sacc[2*p+1], ah, &kfh[4*p+2]);
            }
        }

        // ---- warp-local online softmax ----
        float pm0 = -1e30f, pm1 = -1e30f;
#pragma unroll
        for (int nf = 0; nf < 8; nf++) {
            pm0 = fmaxf(pm0, fmaxf(sacc[nf][0], sacc[nf][1]));
            pm1 = fmaxf(pm1, fmaxf(sacc[nf][2], sacc[nf][3]));
        }
        pm0 = fmaxf(pm0, __shfl_xor_sync(0xffffffffu, pm0, 1));
        pm0 = fmaxf(pm0, __shfl_xor_sync(0xffffffffu, pm0, 2));
        pm1 = fmaxf(pm1, __shfl_xor_sync(0xffffffffu, pm1, 1));
        pm1 = fmaxf(pm1, __shfl_xor_sync(0xffffffffu, pm1, 2));
        float mn0 = fmaxf(m0r, pm0);
        float mn1 = fmaxf(m1r, pm1);
        float f0 = __expf(m0r - mn0);
        float f1 = __expf(m1r - mn1);
        m0r = mn0; m1r = mn1;

        uint32_t ph[4][4];
        float sum0 = 0.f, sum1 = 0.f;
#pragma unroll
        for (int g = 0; g < 4; g++) {
            float q0 = __expf(sacc[2*g][0]   - mn0);
            float q1 = __expf(sacc[2*g][1]   - mn0);
            float q2 = __expf(sacc[2*g][2]   - mn1);
            float q3 = __expf(sacc[2*g][3]   - mn1);
            float s0 = __expf(sacc[2*g+1][0] - mn0);
            float s1 = __expf(sacc[2*g+1][1] - mn0);
            float s2 = __expf(sacc[2*g+1][2] - mn1);
            float s3 = __expf(sacc[2*g+1][3] - mn1);
            sum0 += (q0 + q1) + (s0 + s1);
            sum1 += (q2 + q3) + (s2 + s3);
            ph[g][0] = pack_h2(q0, q1);
            ph[g][1] = pack_h2(q2, q3);
            ph[g][2] = pack_h2(s0, s1);
            ph[g][3] = pack_h2(s2, s3);
        }
        sum0 += __shfl_xor_sync(0xffffffffu, sum0, 1);
        sum0 += __shfl_xor_sync(0xffffffffu, sum0, 2);
        sum1 += __shfl_xor_sync(0xffffffffu, sum1, 1);
        sum1 += __shfl_xor_sync(0xffffffffu, sum1, 2);
        l0r = l0r * f0 + sum0;
        l1r = l1r * f1 + sum1;

        // ---- O = O*fac + P V : 16 rows x 128 d per warp, 1-term ----
#pragma unroll
        for (int nf = 0; nf < 16; nf++) {
            o[nf][0] *= f0; o[nf][1] *= f0;
            o[nf][2] *= f1; o[nf][3] *= f1;
        }
#pragma unroll
        for (int g = 0; g < 4; g++) {
            uint32_t vrow = (uint32_t)((g * 16 + (lane & 15)) * 128);
            uint32_t vcb  = (uint32_t)(lane >> 4) * 16;
#pragma unroll
            for (int p = 0; p < 8; p++) {
                uint32_t vo = stb + (uint32_t)(p >> 2) * 8192 +
                              swz(vrow + (uint32_t)((2*p) & 7) * 16 + vcb);
                uint32_t vh4[4];
                ldsm_x4_t(vh4, sb + AVH_ + vo);
                mma16816(o[2*p],   ph[g], &vh4[0]);
                mma16816(o[2*p+1], ph[g], &vh4[2]);
            }
        }
    }

    // ---- epilogue: normalize, write O as single fp16 (stream = nf>>3) ----
    float li0 = 1.f / l0r, li1 = 1.f / l1r;
    const int rr = wr * 16 + (lane >> 2);
#pragma unroll
    for (int nf = 0; nf < 16; nf++) {
        int strm = nf >> 3;
        int dcol = (nf & 7) * 8 + (lane & 3) * 2;
        size_t base = (size_t)strm * BN * C_
                    + ((size_t)(b * N_ + qt * 128 + rr)) * C_ + h * 64 + dcol;
        *(uint32_t*)&g_Oh[base] = pack_h2(o[nf][0] * li0, o[nf][1] * li0);
        *(uint32_t*)&g_Oh[base + 8 * C_] = pack_h2(o[nf][2] * li1, o[nf][3] * li1);
    }
}

// ---------------------------------------------------------------------------
extern "C" void kernel_launch(void* const* d_in, const int* in_sizes, int n_in,
                              void* d_out, int out_size)
{
    (void)in_sizes; (void)n_in; (void)out_size;
    const float* x1    = (const float*)d_in[0];
    const float* x2    = (const float*)d_in[1];
    const float* Wqkv  = (const float*)d_in[2];
    const float* bqkv  = (const float*)d_in[3];
    const float* Wproj = (const float*)d_in[4];
    const float* bproj = (const float*)d_in[5];
    float* out = (float*)d_out;

    split_all<<<8448, 256>>>(x1, x2, Wqkv, Wproj);

    const int qkv_smem = 99328;   // 1024 + 2x49152 stages (Osm 67584 fits)
    cudaFuncSetAttribute(qkv_gemm, cudaFuncAttributeMaxDynamicSharedMemorySize, qkv_smem);
    qkv_gemm<<<dim3(18, 32, 2), 128, qkv_smem>>>(bqkv);

    const int attn_smem = 98304;
    cudaFuncSetAttribute(attn_mma, cudaFuncAttributeMaxDynamicSharedMemorySize, attn_smem);
    attn_mma<<<dim3(8, 48), 256, attn_smem>>>();

    const int proj_smem = 68608;  // 1024 + max(2x32768 stages, Osm 67584)
    cudaFuncSetAttribute(proj_gemm, cudaFuncAttributeMaxDynamicSharedMemorySize, proj_smem);
    proj_gemm<<<dim3(6, 32, 2), 128, proj_smem>>>(bproj, out);
}

// round 17
// speedup vs baseline: 1.0539x; 1.0539x over previous
#include <cuda_runtime.h>
#include <cuda_fp16.h>
#include <cstdint>

#define B_ 4
#define N_ 1024
#define C_ 768
#define H_ 12
#define BN 4096
#define SCALE 0.125f

// ---------------- scratch (static device globals; no allocations) ----------
__device__ __align__(16) __half g_Qh[(size_t)B_*H_*N_*128];  // SCALE folded
__device__ __align__(16) __half g_Kh[(size_t)B_*H_*N_*128];
__device__ __align__(16) __half g_Vh[(size_t)B_*H_*N_*128];

__device__ __align__(16) __half g_Xh[(size_t)2*BN*C_];
__device__ __align__(16) __half g_Wqh[(size_t)3*C_*C_];
__device__ __align__(16) __half g_Wql[(size_t)3*C_*C_];
__device__ __align__(16) __half g_Wph[(size_t)C_*C_];
__device__ __align__(16) __half g_Oh[(size_t)2*BN*C_];

// ---------------- helpers ---------------------------------------------------
__device__ __forceinline__ uint32_t smem_u32(const void* p) {
    uint32_t a;
    asm("{ .reg .u64 t; cvta.to.shared.u64 t, %1; cvt.u32.u64 %0, t; }"
        : "=r"(a) : "l"(p));
    return a;
}
__device__ __forceinline__ uint32_t swz(uint32_t o) {   // 128B-row swizzle
    return o ^ ((o >> 3) & 0x70);
}
__device__ __forceinline__ void cpa16(uint32_t dst, const void* src) {
    asm volatile("cp.async.cg.shared.global [%0], [%1], 16;" :: "r"(dst), "l"(src));
}
__device__ __forceinline__ void cpa_commit() {
    asm volatile("cp.async.commit_group;" ::: "memory");
}
template<int N>
__device__ __forceinline__ void cpa_wait() {
    asm volatile("cp.async.wait_group %0;" :: "n"(N) : "memory");
}
__device__ __forceinline__ void ldsm_x4(uint32_t* r, uint32_t addr) {
    asm volatile("ldmatrix.sync.aligned.m8n8.x4.shared.b16 {%0,%1,%2,%3}, [%4];"
                 : "=r"(r[0]), "=r"(r[1]), "=r"(r[2]), "=r"(r[3]) : "r"(addr));
}
__device__ __forceinline__ void ldsm_x4_t(uint32_t* r, uint32_t addr) {
    asm volatile("ldmatrix.sync.aligned.m8n8.x4.trans.shared.b16 {%0,%1,%2,%3}, [%4];"
                 : "=r"(r[0]), "=r"(r[1]), "=r"(r[2]), "=r"(r[3]) : "r"(addr));
}
__device__ __forceinline__ void mma16816(float* d, const uint32_t* a, const uint32_t* b) {
    asm volatile(
        "mma.sync.aligned.m16n8k16.row.col.f32.f16.f16.f32 "
        "{%0,%1,%2,%3}, {%4,%5,%6,%7}, {%8,%9}, {%0,%1,%2,%3};"
        : "+f"(d[0]), "+f"(d[1]), "+f"(d[2]), "+f"(d[3])
        : "r"(a[0]), "r"(a[1]), "r"(a[2]), "r"(a[3]), "r"(b[0]), "r"(b[1]));
}
__device__ __forceinline__ uint32_t pack_h2(float a, float b) {
    __half2 t = __floats2half2_rn(a, b);
    return *(uint32_t*)&t;
}

// ---------------------------------------------------------------------------
// fused split kernel: x1,x2,Wproj -> fp16 hi only; Wqkv -> fp16 hi/lo
// ---------------------------------------------------------------------------
#define NX4  (BN * C_ / 4)          // 786432 -> 3072 blocks

__global__ __launch_bounds__(256) void split_all(
    const float* __restrict__ x1, const float* __restrict__ x2,
    const float* __restrict__ Wq, const float* __restrict__ Wp)
{
    int bid = blockIdx.x;
    const float* src;
    __half *hi, *lo;
    size_t off4;
    int i;
    bool wantLo = false;
    if (bid < 3072) {
        src = x1; hi = g_Xh; lo = nullptr; off4 = 0;
        i = bid * 256 + threadIdx.x;
    } else if (bid < 6144) {
        src = x2; hi = g_Xh; lo = nullptr; off4 = NX4;
        i = (bid - 3072) * 256 + threadIdx.x;
    } else if (bid < 7872) {
        src = Wq; hi = g_Wqh; lo = g_Wql; off4 = 0; wantLo = true;
        i = (bid - 6144) * 256 + threadIdx.x;
    } else {
        src = Wp; hi = g_Wph; lo = nullptr; off4 = 0;
        i = (bid - 7872) * 256 + threadIdx.x;
    }
    float4 v = ((const float4*)src)[i];
    size_t o = off4 + (size_t)i;
    ((uint32_t*)hi)[o*2 + 0] = pack_h2(v.x, v.y);
    ((uint32_t*)hi)[o*2 + 1] = pack_h2(v.z, v.w);
    if (wantLo) {
        __half h0 = __float2half(v.x);
        __half h1 = __float2half(v.y);
        __half h2 = __float2half(v.z);
        __half h3 = __float2half(v.w);
        ((uint32_t*)lo)[o*2 + 0] = pack_h2(v.x - __half2float(h0), v.y - __half2float(h1));
        ((uint32_t*)lo)[o*2 + 1] = pack_h2(v.z - __half2float(h2), v.w - __half2float(h3));
    }
}

// ---------------------------------------------------------------------------
// qkv GEMM (r15 proven): 128x128 CTA tile, 128 threads (4 warps, 64x64),
// K-chunk 64, 2-stage cp.async.  Q,K tiles 2-term; V tiles 1-term.
// ---------------------------------------------------------------------------
__device__ __forceinline__ void gemm_issue_chunk(
    uint32_t sbase, const __half* Ah, const __half* Bh, const __half* Bl,
    int m0, int c0, int kc, int tid, bool loadBl)
{
#pragma unroll
    for (int it = 0; it < 8; it++) {
        int idx = tid + it * 128;          // 0..1023: 128 rows x 8 16B-chunks
        int r = idx >> 3, ch8 = idx & 7;
        uint32_t so = swz((uint32_t)(r * 128 + ch8 * 16));
        const size_t aoff = (size_t)(m0 + r) * C_ + kc + ch8 * 8;
        const size_t boff = (size_t)(c0 + r) * C_ + kc + ch8 * 8;
        cpa16(sbase +     0 + so, Ah + aoff);
        cpa16(sbase + 16384 + so, Bh + boff);
        if (loadBl) cpa16(sbase + 32768 + so, Bl + boff);
    }
    cpa_commit();
}

__global__ __launch_bounds__(128, 2) void qkv_gemm(const float* __restrict__ bias)
{
    extern __shared__ char sm[];
    const uint32_t sb = smem_u32(sm) + 1024;
    const int tid = threadIdx.x;
    const int lane = tid & 31, wid = tid >> 5;
    const int wm = wid & 1, wn = wid >> 1;
    const int stream = blockIdx.z;
    const int m0 = blockIdx.y * 128;
    const int c0 = blockIdx.x * 128;
    const int s_tile = c0 / C_;                 // uniform per CTA
    const bool useBl = (s_tile < 2);            // Q,K 2-term; V 1-term

    const __half* __restrict__ Ah = g_Xh + (size_t)stream * BN * C_;
    const __half* __restrict__ Bh = g_Wqh;
    const __half* __restrict__ Bl = g_Wql;

    float acc[4][8][4];
#pragma unroll
    for (int i = 0; i < 4; i++)
#pragma unroll
        for (int j = 0; j < 8; j++)
#pragma unroll
            for (int k = 0; k < 4; k++) acc[i][j][k] = 0.f;

    const int a_r  = wm*64 + (lane & 15);
    const int a_cb = (lane >> 4) * 16;
    const int b_r  = wn*64 + (lane & 7) + ((lane >> 4) & 1)*8;
    const int b_cb = ((lane >> 3) & 1) * 16;

    const int NCH = C_ / 64;   // 12
    gemm_issue_chunk(sb, Ah, Bh, Bl, m0, c0, 0, tid, useBl);

    for (int ch = 0; ch < NCH; ch++) {
        const uint32_t stb = (uint32_t)(ch & 1) * 49152u;
        cpa_wait<0>();
        __syncthreads();
        if (ch + 1 < NCH)
            gemm_issue_chunk(sb + ((ch + 1) & 1) * 49152u,
                             Ah, Bh, Bl, m0, c0, (ch + 1) * 64, tid, useBl);

#pragma unroll
        for (int kk = 0; kk < 4; kk++) {
            uint32_t bfh[16], bfl[16];
#pragma unroll
            for (int p = 0; p < 4; p++) {
                uint32_t bo = swz((uint32_t)((b_r + p*16) * 128 + kk*32 + b_cb));
                ldsm_x4(&bfh[p*4], sb + stb + 16384 + bo);
                if (useBl) ldsm_x4(&bfl[p*4], sb + stb + 32768 + bo);
            }
#pragma unroll
            for (int mf = 0; mf < 4; mf++) {
                uint32_t ao = swz((uint32_t)((a_r + mf*16) * 128 + kk*32 + a_cb));
                uint32_t ah[4];
                ldsm_x4(ah, sb + stb + ao);
#pragma unroll
                for (int p = 0; p < 4; p++) {
                    mma16816(acc[mf][2*p],   ah, &bfh[4*p]);
                    mma16816(acc[mf][2*p+1], ah, &bfh[4*p+2]);
                }
                if (useBl) {
#pragma unroll
                    for (int p = 0; p < 4; p++) {
                        mma16816(acc[mf][2*p],   ah, &bfl[4*p]);
                        mma16816(acc[mf][2*p+1], ah, &bfl[4*p+2]);
                    }
                }
            }
        }
    }
    __syncthreads();

    float* Osm = (float*)(sm + 1024);      // [128][132]
#pragma unroll
    for (int mf = 0; mf < 4; mf++) {
#pragma unroll
        for (int nf = 0; nf < 8; nf++) {
            int row = wm*64 + mf*16 + (lane >> 2);
            int col = wn*64 + nf*8 + (lane & 3)*2;
            Osm[row       * 132 + col    ] = acc[mf][nf][0];
            Osm[row       * 132 + col + 1] = acc[mf][nf][1];
            Osm[(row + 8) * 132 + col    ] = acc[mf][nf][2];
            Osm[(row + 8) * 132 + col + 1] = acc[mf][nf][3];
        }
    }
    __syncthreads();

#pragma unroll
    for (int it = 0; it < 32; it++) {
        int idx = tid + it * 128;
        int r = idx >> 5, j4 = idx & 31;
        float4 v = *(float4*)&Osm[r * 132 + j4 * 4];
        float4 bb = *(const float4*)&bias[c0 + j4 * 4];
        v.x += bb.x; v.y += bb.y; v.z += bb.z; v.w += bb.w;
        int m = m0 + r;
        int cg = c0 + j4 * 4;
        int rem = cg - s_tile * C_;
        int h = rem >> 6, d = rem & 63;
        if (s_tile == 0) { v.x *= SCALE; v.y *= SCALE; v.z *= SCALE; v.w *= SCALE; }
        uint2 hv;
        hv.x = pack_h2(v.x, v.y); hv.y = pack_h2(v.z, v.w);
        int b = m >> 10, n = m & 1023;
        size_t base = ((size_t)(b * H_ + h) * N_ + n) * 128 + stream * 64 + d;
        __half* buf = (s_tile == 0) ? g_Qh : (s_tile == 1) ? g_Kh : g_Vh;
        *(uint2*)&buf[base] = hv;
    }
}

// ---------------------------------------------------------------------------
// proj GEMM (r15 proven): 64x128 CTA tile, 128 threads (4 warps, 32x64),
// K-chunk 64, 2-stage cp.async, 1-term (Oh*Wh).  stage = A 8KB + Bh 16KB.
// ---------------------------------------------------------------------------
__device__ __forceinline__ void proj_issue_chunk(
    uint32_t sbase, const __half* Ah, const __half* Bh,
    int m0, int c0, int kc, int tid)
{
#pragma unroll
    for (int it = 0; it < 4; it++) {       // A: 64 rows x 8 16B-chunks = 512
        int idx = tid + it * 128;
        int r = idx >> 3, ch8 = idx & 7;
        uint32_t so = swz((uint32_t)(r * 128 + ch8 * 16));
        cpa16(sbase + so, Ah + (size_t)(m0 + r) * C_ + kc + ch8 * 8);
    }
#pragma unroll
    for (int it = 0; it < 8; it++) {       // Bh: 128 rows x 8 = 1024
        int idx = tid + it * 128;
        int r = idx >> 3, ch8 = idx & 7;
        uint32_t so = swz((uint32_t)(r * 128 + ch8 * 16));
        cpa16(sbase + 8192 + so, Bh + (size_t)(c0 + r) * C_ + kc + ch8 * 8);
    }
    cpa_commit();
}

__global__ __launch_bounds__(128, 3) void proj_gemm(const float* __restrict__ bias,
                                                    float* __restrict__ outp)
{
    extern __shared__ char sm[];
    const uint32_t sb = smem_u32(sm) + 1024;
    const int tid = threadIdx.x;
    const int lane = tid & 31, wid = tid >> 5;
    const int wm = wid & 1, wn = wid >> 1;
    const int stream = blockIdx.z;
    const int m0 = blockIdx.y * 64;
    const int c0 = blockIdx.x * 128;

    const __half* __restrict__ Ah = g_Oh + (size_t)stream * BN * C_;
    const __half* __restrict__ Bh = g_Wph;

    float acc[2][8][4];
#pragma unroll
    for (int i = 0; i < 2; i++)
#pragma unroll
        for (int j = 0; j < 8; j++)
#pragma unroll
            for (int k = 0; k < 4; k++) acc[i][j][k] = 0.f;

    const int a_r  = wm*32 + (lane & 15);
    const int a_cb = (lane >> 4) * 16;
    const int b_r  = wn*64 + (lane & 7) + ((lane >> 4) & 1)*8;
    const int b_cb = ((lane >> 3) & 1) * 16;

    const int NCH = C_ / 64;   // 12
    proj_issue_chunk(sb, Ah, Bh, m0, c0, 0, tid);

    for (int ch = 0; ch < NCH; ch++) {
        const uint32_t stb = (uint32_t)(ch & 1) * 24576u;
        cpa_wait<0>();
        __syncthreads();
        if (ch + 1 < NCH)
            proj_issue_chunk(sb + ((ch + 1) & 1) * 24576u,
                             Ah, Bh, m0, c0, (ch + 1) * 64, tid);

#pragma unroll
        for (int kk = 0; kk < 4; kk++) {
            uint32_t bfh[16];
#pragma unroll
            for (int p = 0; p < 4; p++) {
                uint32_t bo = swz((uint32_t)((b_r + p*16) * 128 + kk*32 + b_cb));
                ldsm_x4(&bfh[p*4], sb + stb + 8192 + bo);
            }
#pragma unroll
            for (int mf = 0; mf < 2; mf++) {
                uint32_t ao = swz((uint32_t)((a_r + mf*16) * 128 + kk*32 + a_cb));
                uint32_t ah[4];
                ldsm_x4(ah, sb + stb + ao);
#pragma unroll
                for (int p = 0; p < 4; p++) {
                    mma16816(acc[mf][2*p],   ah, &bfh[4*p]);
                    mma16816(acc[mf][2*p+1], ah, &bfh[4*p+2]);
                }
            }
        }
    }
    __syncthreads();

    float* Osm = (float*)(sm + 1024);      // [64][132]
#pragma unroll
    for (int mf = 0; mf < 2; mf++) {
#pragma unroll
        for (int nf = 0; nf < 8; nf++) {
            int row = wm*32 + mf*16 + (lane >> 2);
            int col = wn*64 + nf*8 + (lane & 3)*2;
            Osm[row       * 132 + col    ] = acc[mf][nf][0];
            Osm[row       * 132 + col + 1] = acc[mf][nf][1];
            Osm[(row + 8) * 132 + col    ] = acc[mf][nf][2];
            Osm[(row + 8) * 132 + col + 1] = acc[mf][nf][3];
        }
    }
    __syncthreads();

    float* Y = outp + (size_t)stream * BN * C_;
#pragma unroll
    for (int it = 0; it < 16; it++) {
        int idx = tid + it * 128;
        int r = idx >> 5, j4 = idx & 31;
        float4 v = *(float4*)&Osm[r * 132 + j4 * 4];
        float4 bb = *(const float4*)&bias[c0 + j4 * 4];
        v.x += bb.x; v.y += bb.y; v.z += bb.z; v.w += bb.w;
        *(float4*)&Y[(size_t)(m0 + r) * C_ + c0 + j4 * 4] = v;
    }
}

// ---------------------------------------------------------------------------
// flash attention: 64 q-rows/CTA, 128 threads (4 warps x 16 rows), 2 CTAs/SM.
// S = Qh*Kh (1-term).  PV 1-term.  Warp-local softmax, register P,
// cp.async 2-stage K/V, 1 barrier/tile.
// smem: Q 16KB @ 65536? layout: 2 stages x (Kh 16KB + Vh 16KB) + Q 16KB = 80KB
// ---------------------------------------------------------------------------
#define ASTG_ 32768u
#define AKH_ 0u
#define AVH_ 16384u
#define AQH_ 65536u
#define ATTN_SMEM 81920

__device__ __forceinline__ void attn_issue_kv(
    uint32_t sb, uint32_t stb,
    const __half* kh_g, const __half* vh_g, int tid)
{
#pragma unroll
    for (int it = 0; it < 8; it++) {
        int idx = tid + it * 128;          // 0..1023: 64 rows x 16 16B-chunks
        int row = idx >> 4, ch = idx & 15;
        int src = row * 128 + ch * 8;
        uint32_t dst = stb + (uint32_t)(ch >> 3) * 8192 + swz((uint32_t)(row * 128 + (ch & 7) * 16));
        cpa16(sb + AKH_ + dst, kh_g + src);
        cpa16(sb + AVH_ + dst, vh_g + src);
    }
    cpa_commit();
}

__global__ __launch_bounds__(128, 2) void attn_mma()
{
    extern __shared__ char sm[];
    const uint32_t sb = smem_u32(sm);

    const int tid = threadIdx.x;
    const int lane = tid & 31, wr = tid >> 5;   // 4 warps: rows wr*16..+15
    const int qt = blockIdx.x, bh = blockIdx.y;
    const int b = bh / H_, h = bh - b * H_;
    const size_t kvb = (size_t)bh * N_ * 128;

    const __half* kh_g = g_Kh + kvb;
    const __half* vh_g = g_Vh + kvb;

    attn_issue_kv(sb, 0, kh_g, vh_g, tid);

    {
        const __half* qh_g = g_Qh + kvb + (size_t)qt * 64 * 128;
#pragma unroll
        for (int it = 0; it < 8; it++) {
            int idx = tid + it * 128;          // 0..1023: 64 rows x 16 chunks
            int row = idx >> 4, ch = idx & 15;
            uint32_t dst = (uint32_t)(ch >> 3) * 8192 + swz((uint32_t)(row * 128 + (ch & 7) * 16));
            *(uint4*)(sm + AQH_ + dst) = *(const uint4*)(qh_g + row * 128 + ch * 8);
        }
    }

    float m0r = -1e30f, m1r = -1e30f, l0r = 0.f, l1r = 0.f;
    float o[16][4];
#pragma unroll
    for (int i = 0; i < 16; i++)
#pragma unroll
        for (int j = 0; j < 4; j++) o[i][j] = 0.f;

    const int qrow = wr * 16 + (lane & 15);
    const int k_r  = (lane & 7) + ((lane >> 4) & 1) * 8;
    const int k_cb = ((lane >> 3) & 1) * 16;

    for (int kt = 0; kt < 16; kt++) {
        const uint32_t stb = (uint32_t)(kt & 1) * ASTG_;
        cpa_wait<0>();
        __syncthreads();
        if (kt < 15)
            attn_issue_kv(sb, (uint32_t)((kt + 1) & 1) * ASTG_,
                          kh_g + (size_t)(kt + 1) * 64 * 128,
                          vh_g + (size_t)(kt + 1) * 64 * 128, tid);

        // ---- S = Q K^T : 16 rows x 64 cols per warp, k=128, 1-term ----
        float sacc[8][4];
#pragma unroll
        for (int i = 0; i < 8; i++)
#pragma unroll
            for (int j = 0; j < 4; j++) sacc[i][j] = 0.f;

#pragma unroll
        for (int k16 = 0; k16 < 8; k16++) {
            uint32_t qo = (uint32_t)(k16 >> 2) * 8192 +
                          swz((uint32_t)(qrow * 128 + (k16 & 3) * 32 + (lane >> 4) * 16));
            uint32_t ah[4];
            ldsm_x4(ah, sb + AQH_ + qo);
            uint32_t kpl = stb + (uint32_t)(k16 >> 2) * 8192;
            uint32_t kcb = (uint32_t)((k16 & 3) * 32) + k_cb;
            uint32_t kfh[16];
#pragma unroll
            for (int p = 0; p < 4; p++) {
                uint32_t ko = kpl + swz((uint32_t)((k_r + p*16) * 128) + kcb);
                ldsm_x4(&kfh[4*p], sb + AKH_ + ko);
            }
#pragma unroll
            for (int p = 0; p < 4; p++) {
                mma16816(sacc[2*p],   ah, &kfh[4*p]);
                mma16816(sacc[2*p+1], ah, &kfh[4*p+2]);
            }
        }

        // ---- warp-local online softmax ----
        float pm0 = -1e30f, pm1 = -1e30f;
#pragma unroll
        for (int nf = 0; nf < 8; nf++) {
            pm0 = fmaxf(pm0, fmaxf(sacc[nf][0], sacc[nf][1]));
            pm1 = fmaxf(pm1, fmaxf(sacc[nf][2], sacc[nf][3]));
        }
        pm0 = fmaxf(pm0, __shfl_xor_sync(0xffffffffu, pm0, 1));
        pm0 = fmaxf(pm0, __shfl_xor_sync(0xffffffffu, pm0, 2));
        pm1 = fmaxf(pm1, __shfl_xor_sync(0xffffffffu, pm1, 1));
        pm1 = fmaxf(pm1, __shfl_xor_sync(0xffffffffu, pm1, 2));
        float mn0 = fmaxf(m0r, pm0);
        float mn1 = fmaxf(m1r, pm1);
        float f0 = __expf(m0r - mn0);
        float f1 = __expf(m1r - mn1);
        m0r = mn0; m1r = mn1;

        uint32_t ph[4][4];
        float sum0 = 0.f, sum1 = 0.f;
#pragma unroll
        for (int g = 0; g < 4; g++) {
            float q0 = __expf(sacc[2*g][0]   - mn0);
            float q1 = __expf(sacc[2*g][1]   - mn0);
            float q2 = __expf(sacc[2*g][2]   - mn1);
            float q3 = __expf(sacc[2*g][3]   - mn1);
            float s0 = __expf(sacc[2*g+1][0] - mn0);
            float s1 = __expf(sacc[2*g+1][1] - mn0);
            float s2 = __expf(sacc[2*g+1][2] - mn1);
            float s3 = __expf(sacc[2*g+1][3] - mn1);
            sum0 += (q0 + q1) + (s0 + s1);
            sum1 += (q2 + q3) + (s2 + s3);
            ph[g][0] = pack_h2(q0, q1);
            ph[g][1] = pack_h2(q2, q3);
            ph[g][2] = pack_h2(s0, s1);
            ph[g][3] = pack_h2(s2, s3);
        }
        sum0 += __shfl_xor_sync(0xffffffffu, sum0, 1);
        sum0 += __shfl_xor_sync(0xffffffffu, sum0, 2);
        sum1 += __shfl_xor_sync(0xffffffffu, sum1, 1);
        sum1 += __shfl_xor_sync(0xffffffffu, sum1, 2);
        l0r = l0r * f0 + sum0;
        l1r = l1r * f1 + sum1;

        // ---- O = O*fac + P V : 16 rows x 128 d per warp, 1-term ----
#pragma unroll
        for (int nf = 0; nf < 16; nf++) {
            o[nf][0] *= f0; o[nf][1] *= f0;
            o[nf][2] *= f1; o[nf][3] *= f1;
        }
#pragma unroll
        for (int g = 0; g < 4; g++) {
            uint32_t vrow = (uint32_t)((g * 16 + (lane & 15)) * 128);
            uint32_t vcb  = (uint32_t)(lane >> 4) * 16;
#pragma unroll
            for (int p = 0; p < 8; p++) {
                uint32_t vo = stb + (uint32_t)(p >> 2) * 8192 +
                              swz(vrow + (uint32_t)((2*p) & 7) * 16 + vcb);
                uint32_t vh4[4];
                ldsm_x4_t(vh4, sb + AVH_ + vo);
                mma16816(o[2*p],   ph[g], &vh4[0]);
                mma16816(o[2*p+1], ph[g], &vh4[2]);
            }
        }
    }

    // ---- epilogue: normalize, write O as single fp16 (stream = nf>>3) ----
    float li0 = 1.f / l0r, li1 = 1.f / l1r;
    const int rr = wr * 16 + (lane >> 2);
#pragma unroll
    for (int nf = 0; nf < 16; nf++) {
        int strm = nf >> 3;
        int dcol = (nf & 7) * 8 + (lane & 3) * 2;
        size_t base = (size_t)strm * BN * C_
                    + ((size_t)(b * N_ + qt * 64 + rr)) * C_ + h * 64 + dcol;
        *(uint32_t*)&g_Oh[base] = pack_h2(o[nf][0] * li0, o[nf][1] * li0);
        *(uint32_t*)&g_Oh[base + 8 * C_] = pack_h2(o[nf][2] * li1, o[nf][3] * li1);
    }
}

// ---------------------------------------------------------------------------
extern "C" void kernel_launch(void* const* d_in, const int* in_sizes, int n_in,
                              void* d_out, int out_size)
{
    (void)in_sizes; (void)n_in; (void)out_size;
    const float* x1    = (const float*)d_in[0];
    const float* x2    = (const float*)d_in[1];
    const float* Wqkv  = (const float*)d_in[2];
    const float* bqkv  = (const float*)d_in[3];
    const float* Wproj = (const float*)d_in[4];
    const float* bproj = (const float*)d_in[5];
    float* out = (float*)d_out;

    split_all<<<8448, 256>>>(x1, x2, Wqkv, Wproj);

    const int qkv_smem = 99328;   // 1024 + 2x49152 stages (Osm 67584 fits)
    cudaFuncSetAttribute(qkv_gemm, cudaFuncAttributeMaxDynamicSharedMemorySize, qkv_smem);
    qkv_gemm<<<dim3(18, 32, 2), 128, qkv_smem>>>(bqkv);

    cudaFuncSetAttribute(attn_mma, cudaFuncAttributeMaxDynamicSharedMemorySize, ATTN_SMEM);
    attn_mma<<<dim3(16, 48), 128, ATTN_SMEM>>>();

    const int proj_smem = 50176;  // 1024 + 2x24576 stages (Osm 33792 fits)
    cudaFuncSetAttribute(proj_gemm, cudaFuncAttributeMaxDynamicSharedMemorySize, proj_smem);
    proj_gemm<<<dim3(6, 64, 2), 128, proj_smem>>>(bproj, out);
}